// round 12
// baseline (speedup 1.0000x reference)
#include <cuda_runtime.h>
#include <mma.h>
#include <cstdint>

using namespace nvcuda;

#define N_  4
#define C_  128
#define H_  128
#define W_  128
#define OC  8
#define OH  256
#define OW  256
#define HW  (H_*W_)
#define NT  72
#define NTP 80      // g_S t-stride
#define BLD 84      // smem B ldm (bank-conflict-free, mult of 4)

// S[n][t][hw], t = tap*8 + o  (t in [0,80), rows 72..79 pad)
__device__ float g_S[N_ * NTP * HW];
// off[n][o][h][w]
__device__ float g_off[N_ * OC * HW];

__device__ __forceinline__ float to_tf32(float f) {
    float r;
    asm("cvt.rna.tf32.f32 %0, %1;" : "=f"(r) : "f"(f));
    return r;
}

// ---------------------------------------------------------------------------
// Kernel 1: pointwise GEMM S[t,px] = sum_c W[t,c]*x[c,px], wmma tf32,
// 2x5 register blocking, B padded to ldm=84. Grid 256 = 4n x 64 tiles.
// ---------------------------------------------------------------------------
#define PXT  256
#define SM_XT_F  0                          // 64c x 256px
#define SM_B_F   (64*PXT)                   // 128c x BLD
#define SM_TOT_B ((64*PXT + 128*BLD) * 4)

__global__ __launch_bounds__(256, 2) void conv_gemm_kernel(
    const float* __restrict__ x,
    const float* __restrict__ wt)    // [o][c][3][3]
{
    extern __shared__ float sm[];
    float* xt = sm + SM_XT_F;        // xt[c][px] c in [0,64) local
    float* Wt = sm + SM_B_F;         // Wt[c][t]  c in [0,128), ldm=BLD

    const int tid = threadIdx.x;
    const int bid = blockIdx.x;
    const int n   = bid >> 6;
    const int px0 = (bid & 63) * PXT;
    const int wid = tid >> 5;

    // Stage B once (pre-rounded): Wt[c][t] = wt[o][c][tap], t = tap*8+o
    for (int i = tid; i < 128*BLD; i += 256) {
        int c = i / BLD, t = i - c*BLD;
        float v = 0.f;
        if (t < NT) v = to_tf32(wt[(((size_t)(t & 7))*C_ + c)*9 + (t >> 3)]);
        Wt[i] = v;
    }

    wmma::fragment<wmma::accumulator, 16, 16, 8, float> acc[2][5];
#pragma unroll
    for (int i = 0; i < 2; i++)
#pragma unroll
        for (int tt = 0; tt < 5; tt++) wmma::fill_fragment(acc[i][tt], 0.f);

    const float* xn = x + (size_t)n*C_*HW + px0;

    for (int s = 0; s < 2; s++) {
        __syncthreads();
        for (int i = tid; i < 64*(PXT/4); i += 256) {
            int c = i >> 6, p4 = (i & 63)*4;
            float4 v = *reinterpret_cast<const float4*>(xn + (size_t)(s*64 + c)*HW + p4);
            v.x = to_tf32(v.x); v.y = to_tf32(v.y);
            v.z = to_tf32(v.z); v.w = to_tf32(v.w);
            *reinterpret_cast<float4*>(xt + c*PXT + p4) = v;
        }
        __syncthreads();

#pragma unroll
        for (int kl = 0; kl < 8; kl++) {
            wmma::fragment<wmma::matrix_a, 16, 16, 8, wmma::precision::tf32, wmma::col_major> a0, a1;
            wmma::load_matrix_sync(a0, xt + (kl*8)*PXT + 32*wid,      PXT);
            wmma::load_matrix_sync(a1, xt + (kl*8)*PXT + 32*wid + 16, PXT);
#pragma unroll
            for (int tt = 0; tt < 5; tt++) {
                wmma::fragment<wmma::matrix_b, 16, 16, 8, wmma::precision::tf32, wmma::row_major> b;
                wmma::load_matrix_sync(b, Wt + (s*64 + kl*8)*BLD + tt*16, BLD);
                wmma::mma_sync(acc[0][tt], a0, b, acc[0][tt]);
                wmma::mma_sync(acc[1][tt], a1, b, acc[1][tt]);
            }
        }
    }

    float* Sp = g_S + (size_t)n*NTP*HW + px0 + 32*wid;
#pragma unroll
    for (int i = 0; i < 2; i++)
#pragma unroll
        for (int tt = 0; tt < 5; tt++)
            wmma::store_matrix_sync(Sp + i*16 + (size_t)(tt*16)*HW, acc[i][tt],
                                    HW, wmma::mem_col_major);
}

// ---------------------------------------------------------------------------
// Kernel 2: shift-add epilogue
// ---------------------------------------------------------------------------
__global__ __launch_bounds__(256) void shift_add_kernel(
    const float* __restrict__ bs)
{
    const int b = blockIdx.x;
    const int n = b >> 7;
    const int h = b & (H_-1);
    const int tid = threadIdx.x;
    const int w  = tid & 127;
    const int og = (tid >> 7) * 4;

    const float* Sn = g_S + (size_t)n*NTP*HW;

#pragma unroll
    for (int oo = 0; oo < 4; oo++) {
        const int o = og + oo;
        float s = __ldg(&bs[o]);
#pragma unroll
        for (int ky = 0; ky < 3; ky++) {
            const int hh = h + ky - 1;
            if ((unsigned)hh >= H_) continue;
#pragma unroll
            for (int kx = 0; kx < 3; kx++) {
                const int ww = w + kx - 1;
                if ((unsigned)ww >= W_) continue;
                const int t = (ky*3 + kx)*8 + o;
                s += Sn[(size_t)t*HW + hh*W_ + ww];
            }
        }
        g_off[(((size_t)n*OC + o)*H_ + h)*W_ + w] = s;
    }
}

// ---------------------------------------------------------------------------
// Kernel 3: bilinear sampling + pixel shuffle. Fast path: one LDG.128 per
// corner-row (covers both x-corners), SEL extraction; edge threads use the
// original scalar clamped path.
// ---------------------------------------------------------------------------
__global__ __launch_bounds__(256) void sample_kernel(
    const float* __restrict__ x,
    float* __restrict__ out)
{
    __shared__ float soff[4][W_];

    const int b  = blockIdx.x;
    const int kh = b & 1;
    const int h  = (b >> 1) & (H_-1);
    const int n  = b >> 8;
    const int tid = threadIdx.x;

    for (int i = tid; i < 4*W_; i += 256) {
        int j  = i >> 7;
        int ww = i & (W_-1);
        int o  = (kh*2 + (j >> 1))*2 + (j & 1);
        soff[j][ww] = g_off[(((size_t)n*OC + o)*H_ + h)*W_ + ww];
    }
    __syncthreads();

    const int kw = tid & 1;
    const int w  = tid >> 1;

    float sy = (float)h + soff[kw*2    ][w];
    float sx = (float)w + soff[kw*2 + 1][w];
    float y0f = floorf(sy), x0f = floorf(sx);
    int   y0 = (int)y0f,   x0 = (int)x0f;
    float fy = sy - y0f,   fx = sx - x0f;

    float cw0 = (1.f - fy) * (1.f - fx);
    float cw1 = (1.f - fy) * fx;
    float cw2 = fy * (1.f - fx);
    float cw3 = fy * fx;

    // y validity -> weight zeroing; clamped rows are safe to read
    if (!((unsigned)y0       < (unsigned)H_)) { cw0 = 0.f; cw1 = 0.f; }
    if (!((unsigned)(y0 + 1) < (unsigned)H_)) { cw2 = 0.f; cw3 = 0.f; }
    const int ytc = min(max(y0,     0), H_-1);
    const int ybc = min(max(y0 + 1, 0), H_-1);

    const bool fast = ((unsigned)x0 < (unsigned)(W_-1));   // x0 in [0,126]
    // Edge path precompute
    int xl = min(max(x0,     0), W_-1);
    int xr = min(max(x0 + 1, 0), W_-1);
    float ecw0 = cw0, ecw1 = cw1, ecw2 = cw2, ecw3 = cw3;
    if (!((unsigned)x0       < (unsigned)W_)) { ecw0 = 0.f; ecw2 = 0.f; }
    if (!((unsigned)(x0 + 1) < (unsigned)W_)) { ecw1 = 0.f; ecw3 = 0.f; }

    const int xa = x0 & ~3;
    const int q  = x0 & 3;
    const bool need5 = (q == 3);

    const float* xp = x + (size_t)n*C_*HW;
    float* op = out + ((size_t)n*C_)*OH*OW + (size_t)(2*h + kh)*OW + (2*w + kw);

    const int rowt = ytc*W_;
    const int rowb = ybc*W_;

#pragma unroll 2
    for (int c = 0; c < C_; c++) {
        float r;
        if (fast) {
            float4 Ft = __ldg(reinterpret_cast<const float4*>(xp + rowt + xa));
            float4 Fb = __ldg(reinterpret_cast<const float4*>(xp + rowb + xa));
            float t4 = 0.f, b4 = 0.f;
            if (need5) {
                t4 = __ldg(xp + rowt + x0 + 1);
                b4 = __ldg(xp + rowb + x0 + 1);
            }
            float vtl = (q == 0) ? Ft.x : (q == 1) ? Ft.y : (q == 2) ? Ft.z : Ft.w;
            float vtr = (q == 0) ? Ft.y : (q == 1) ? Ft.z : (q == 2) ? Ft.w : t4;
            float vbl = (q == 0) ? Fb.x : (q == 1) ? Fb.y : (q == 2) ? Fb.z : Fb.w;
            float vbr = (q == 0) ? Fb.y : (q == 1) ? Fb.z : (q == 2) ? Fb.w : b4;
            r = vtl*cw0;
            r = fmaf(vtr, cw1, r);
            r = fmaf(vbl, cw2, r);
            r = fmaf(vbr, cw3, r);
        } else {
            float vtl = __ldg(xp + rowt + xl);
            float vtr = __ldg(xp + rowt + xr);
            float vbl = __ldg(xp + rowb + xl);
            float vbr = __ldg(xp + rowb + xr);
            r = vtl*ecw0;
            r = fmaf(vtr, ecw1, r);
            r = fmaf(vbl, ecw2, r);
            r = fmaf(vbr, ecw3, r);
        }
        *op = r;
        xp += HW;
        op += OH*OW;
    }
}

// ---------------------------------------------------------------------------
extern "C" void kernel_launch(void* const* d_in, const int* in_sizes, int n_in,
                              void* d_out, int out_size)
{
    const float* x  = (const float*)d_in[0];
    const float* wt = (const float*)d_in[1];
    const float* bs = (const float*)d_in[2];
    float* out = (float*)d_out;

    cudaFuncSetAttribute(conv_gemm_kernel,
                         cudaFuncAttributeMaxDynamicSharedMemorySize, SM_TOT_B);

    conv_gemm_kernel<<<256, 256, SM_TOT_B>>>(x, wt);
    shift_add_kernel<<<512, 256>>>(bs);
    sample_kernel<<<N_*H_*2, 256>>>(x, out);
}

// round 13
// speedup vs baseline: 1.7795x; 1.7795x over previous
#include <cuda_runtime.h>
#include <mma.h>
#include <cstdint>

using namespace nvcuda;

#define N_  4
#define C_  128
#define H_  128
#define W_  128
#define OC  8
#define OH  256
#define OW  256
#define HW  (H_*W_)
#define NT  72
#define NTP 80      // g_S t-stride
#define BLD 84      // smem B ldm

// S[n][t][hw], t = tap*8 + o
__device__ float g_S[N_ * NTP * HW];
// off[n][o][h][w]
__device__ float g_off[N_ * OC * HW];

__device__ __forceinline__ float to_tf32(float f) {
    float r;
    asm("cvt.rna.tf32.f32 %0, %1;" : "=f"(r) : "f"(f));
    return r;
}

// ---------------------------------------------------------------------------
// Kernel 1: pointwise GEMM S[t,px] = sum_c W[t,c]*x[c,px], wmma tf32.
// Occupancy-first shape: warp = 16px x 80t (acc 1x5 = 40 regs), block =
// 256 thr = 128px, x and B staged in 64-channel chunks (smem ~54 KB) ->
// 4 blocks/SM, 32 warps. Grid 512 = 4n x 128 tiles (single wave).
// ---------------------------------------------------------------------------
#define PXT  128
#define SM_XT_F  0                          // 64c x 128px
#define SM_B_F   (64*PXT)                   // 64c x BLD
#define SM_TOT_B ((64*PXT + 64*BLD) * 4)

__global__ __launch_bounds__(256, 4) void conv_gemm_kernel(
    const float* __restrict__ x,
    const float* __restrict__ wt)    // [o][c][3][3]
{
    extern __shared__ float sm[];
    float* xt = sm + SM_XT_F;        // xt[c][px], c local in [0,64)
    float* Wt = sm + SM_B_F;         // Wt[c][t],  c local in [0,64), ldm=BLD

    const int tid = threadIdx.x;
    const int bid = blockIdx.x;
    const int n   = bid >> 7;
    const int px0 = (bid & 127) * PXT;
    const int wid = tid >> 5;        // warp: px rows [16*wid, 16*wid+16)

    wmma::fragment<wmma::accumulator, 16, 16, 8, float> acc[5];
#pragma unroll
    for (int tt = 0; tt < 5; tt++) wmma::fill_fragment(acc[tt], 0.f);

    const float* xn = x + (size_t)n*C_*HW + px0;

    for (int s = 0; s < 2; s++) {
        __syncthreads();
        // Stage 64 channels of B (pre-rounded): Wt[c][t] = wt[o][s*64+c][tap]
        for (int i = tid; i < 64*BLD; i += 256) {
            int c = i / BLD, t = i - c*BLD;
            float v = 0.f;
            if (t < NT)
                v = to_tf32(wt[(((size_t)(t & 7))*C_ + (s*64 + c))*9 + (t >> 3)]);
            Wt[i] = v;
        }
        // Stage 64 channels of x (pre-rounded)
        for (int i = tid; i < 64*(PXT/4); i += 256) {
            int c = i >> 5, p4 = (i & 31)*4;
            float4 v = *reinterpret_cast<const float4*>(xn + (size_t)(s*64 + c)*HW + p4);
            v.x = to_tf32(v.x); v.y = to_tf32(v.y);
            v.z = to_tf32(v.z); v.w = to_tf32(v.w);
            *reinterpret_cast<float4*>(xt + c*PXT + p4) = v;
        }
        __syncthreads();

#pragma unroll
        for (int kl = 0; kl < 8; kl++) {
            wmma::fragment<wmma::matrix_a, 16, 16, 8, wmma::precision::tf32, wmma::col_major> a;
            wmma::load_matrix_sync(a, xt + (kl*8)*PXT + 16*wid, PXT);
#pragma unroll
            for (int tt = 0; tt < 5; tt++) {
                wmma::fragment<wmma::matrix_b, 16, 16, 8, wmma::precision::tf32, wmma::row_major> b;
                wmma::load_matrix_sync(b, Wt + (kl*8)*BLD + tt*16, BLD);
                wmma::mma_sync(acc[tt], a, b, acc[tt]);
            }
        }
    }

    // Store C col-major straight into S[t][px]: col stride = HW
    float* Sp = g_S + (size_t)n*NTP*HW + px0 + 16*wid;
#pragma unroll
    for (int tt = 0; tt < 5; tt++)
        wmma::store_matrix_sync(Sp + (size_t)(tt*16)*HW, acc[tt], HW, wmma::mem_col_major);
}

// ---------------------------------------------------------------------------
// Kernel 2: shift-add epilogue
// ---------------------------------------------------------------------------
__global__ __launch_bounds__(256) void shift_add_kernel(
    const float* __restrict__ bs)
{
    const int b = blockIdx.x;
    const int n = b >> 7;
    const int h = b & (H_-1);
    const int tid = threadIdx.x;
    const int w  = tid & 127;
    const int og = (tid >> 7) * 4;

    const float* Sn = g_S + (size_t)n*NTP*HW;

#pragma unroll
    for (int oo = 0; oo < 4; oo++) {
        const int o = og + oo;
        float s = __ldg(&bs[o]);
#pragma unroll
        for (int ky = 0; ky < 3; ky++) {
            const int hh = h + ky - 1;
            if ((unsigned)hh >= H_) continue;
#pragma unroll
            for (int kx = 0; kx < 3; kx++) {
                const int ww = w + kx - 1;
                if ((unsigned)ww >= W_) continue;
                const int t = (ky*3 + kx)*8 + o;
                s += Sn[(size_t)t*HW + hh*W_ + ww];
            }
        }
        g_off[(((size_t)n*OC + o)*H_ + h)*W_ + w] = s;
    }
}

// ---------------------------------------------------------------------------
// Kernel 3: bilinear sampling + pixel shuffle (r3 measured-best gather,
// scalar loads only). One block per (n, h, kh): 256 threads, tid = w*2+kw.
// ---------------------------------------------------------------------------
__global__ __launch_bounds__(256) void sample_kernel(
    const float* __restrict__ x,
    float* __restrict__ out)
{
    __shared__ float soff[4][W_];

    const int b  = blockIdx.x;
    const int kh = b & 1;
    const int h  = (b >> 1) & (H_-1);
    const int n  = b >> 8;
    const int tid = threadIdx.x;

    for (int i = tid; i < 4*W_; i += 256) {
        int j  = i >> 7;
        int ww = i & (W_-1);
        int o  = (kh*2 + (j >> 1))*2 + (j & 1);
        soff[j][ww] = g_off[(((size_t)n*OC + o)*H_ + h)*W_ + ww];
    }
    __syncthreads();

    const int kw = tid & 1;
    const int w  = tid >> 1;

    float sy = (float)h + soff[kw*2    ][w];
    float sx = (float)w + soff[kw*2 + 1][w];
    float y0f = floorf(sy), x0f = floorf(sx);
    int   y0 = (int)y0f,   x0 = (int)x0f;
    float fy = sy - y0f,   fx = sx - x0f;

    float cw[4];
    cw[0] = (1.f - fy) * (1.f - fx);
    cw[1] = (1.f - fy) * fx;
    cw[2] = fy * (1.f - fx);
    cw[3] = fy * fx;
    int ci[4];
#pragma unroll
    for (int k = 0; k < 4; k++) {
        int yi = y0 + (k >> 1);
        int xi = x0 + (k & 1);
        bool valid = ((unsigned)yi < H_) && ((unsigned)xi < W_);
        int yc = min(max(yi, 0), H_-1);
        int xc = min(max(xi, 0), W_-1);
        ci[k] = yc*W_ + xc;
        if (!valid) cw[k] = 0.f;
    }

    const float* xp = x + (size_t)n*C_*HW;
    float* op = out + ((size_t)n*C_)*OH*OW + (size_t)(2*h + kh)*OW + (2*w + kw);

#pragma unroll 2
    for (int c = 0; c < C_; c++) {
        float v0 = __ldg(xp + ci[0]);
        float v1 = __ldg(xp + ci[1]);
        float v2 = __ldg(xp + ci[2]);
        float v3 = __ldg(xp + ci[3]);
        float r = v0*cw[0];
        r = fmaf(v1, cw[1], r);
        r = fmaf(v2, cw[2], r);
        r = fmaf(v3, cw[3], r);
        *op = r;
        xp += HW;
        op += OH*OW;
    }
}

// ---------------------------------------------------------------------------
extern "C" void kernel_launch(void* const* d_in, const int* in_sizes, int n_in,
                              void* d_out, int out_size)
{
    const float* x  = (const float*)d_in[0];
    const float* wt = (const float*)d_in[1];
    const float* bs = (const float*)d_in[2];
    float* out = (float*)d_out;

    cudaFuncSetAttribute(conv_gemm_kernel,
                         cudaFuncAttributeMaxDynamicSharedMemorySize, SM_TOT_B);

    conv_gemm_kernel<<<512, 256, SM_TOT_B>>>(x, wt);
    shift_add_kernel<<<512, 256>>>(bs);
    sample_kernel<<<N_*H_*2, 256>>>(x, out);
}

// round 14
// speedup vs baseline: 2.0446x; 1.1490x over previous
#include <cuda_runtime.h>
#include <mma.h>
#include <cstdint>

using namespace nvcuda;

#define N_  4
#define C_  128
#define H_  128
#define W_  128
#define OC  8
#define OH  256
#define OW  256
#define HW  (H_*W_)
#define NT  72
#define NTP 80      // g_S t-stride
#define BLD 84      // smem B ldm (bank-conflict-free)

// S[n][t][hw], t = tap*8 + o  (t in [0,80), rows 72..79 pad)
__device__ float g_S[N_ * NTP * HW];

__device__ __forceinline__ float to_tf32(float f) {
    float r;
    asm("cvt.rna.tf32.f32 %0, %1;" : "=f"(r) : "f"(f));
    return r;
}

// ---------------------------------------------------------------------------
// Kernel 1: pointwise GEMM S[t,px] = sum_c W[t,c]*x[c,px], wmma tf32,
// 2x5 register blocking, B ldm=84, grid 256 = 4n x 64 tiles (single wave).
// (r12 conv, measured best: 36.3 us)
// ---------------------------------------------------------------------------
#define PXT  256
#define SM_XT_F  0                          // 64c x 256px
#define SM_B_F   (64*PXT)                   // 128c x BLD
#define SM_TOT_B ((64*PXT + 128*BLD) * 4)

__global__ __launch_bounds__(256, 2) void conv_gemm_kernel(
    const float* __restrict__ x,
    const float* __restrict__ wt)    // [o][c][3][3]
{
    extern __shared__ float sm[];
    float* xt = sm + SM_XT_F;        // xt[c][px], c local in [0,64)
    float* Wt = sm + SM_B_F;         // Wt[c][t],  c in [0,128), ldm=BLD

    const int tid = threadIdx.x;
    const int bid = blockIdx.x;
    const int n   = bid >> 6;
    const int px0 = (bid & 63) * PXT;
    const int wid = tid >> 5;

    // Stage B once (pre-rounded): Wt[c][t] = wt[o][c][tap], t = tap*8+o
    for (int i = tid; i < 128*BLD; i += 256) {
        int c = i / BLD, t = i - c*BLD;
        float v = 0.f;
        if (t < NT) v = to_tf32(wt[(((size_t)(t & 7))*C_ + c)*9 + (t >> 3)]);
        Wt[i] = v;
    }

    wmma::fragment<wmma::accumulator, 16, 16, 8, float> acc[2][5];
#pragma unroll
    for (int i = 0; i < 2; i++)
#pragma unroll
        for (int tt = 0; tt < 5; tt++) wmma::fill_fragment(acc[i][tt], 0.f);

    const float* xn = x + (size_t)n*C_*HW + px0;

    for (int s = 0; s < 2; s++) {
        __syncthreads();
        for (int i = tid; i < 64*(PXT/4); i += 256) {
            int c = i >> 6, p4 = (i & 63)*4;
            float4 v = *reinterpret_cast<const float4*>(xn + (size_t)(s*64 + c)*HW + p4);
            v.x = to_tf32(v.x); v.y = to_tf32(v.y);
            v.z = to_tf32(v.z); v.w = to_tf32(v.w);
            *reinterpret_cast<float4*>(xt + c*PXT + p4) = v;
        }
        __syncthreads();

#pragma unroll
        for (int kl = 0; kl < 8; kl++) {
            wmma::fragment<wmma::matrix_a, 16, 16, 8, wmma::precision::tf32, wmma::col_major> a0, a1;
            wmma::load_matrix_sync(a0, xt + (kl*8)*PXT + 32*wid,      PXT);
            wmma::load_matrix_sync(a1, xt + (kl*8)*PXT + 32*wid + 16, PXT);
#pragma unroll
            for (int tt = 0; tt < 5; tt++) {
                wmma::fragment<wmma::matrix_b, 16, 16, 8, wmma::precision::tf32, wmma::row_major> b;
                wmma::load_matrix_sync(b, Wt + (s*64 + kl*8)*BLD + tt*16, BLD);
                wmma::mma_sync(acc[0][tt], a0, b, acc[0][tt]);
                wmma::mma_sync(acc[1][tt], a1, b, acc[1][tt]);
            }
        }
    }

    float* Sp = g_S + (size_t)n*NTP*HW + px0 + 32*wid;
#pragma unroll
    for (int i = 0; i < 2; i++)
#pragma unroll
        for (int tt = 0; tt < 5; tt++)
            wmma::store_matrix_sync(Sp + i*16 + (size_t)(tt*16)*HW, acc[i][tt],
                                    HW, wmma::mem_col_major);
}

// ---------------------------------------------------------------------------
// Kernel 2: fused shift-add + bilinear sampling + pixel shuffle.
// One block per (n, h, kh). Staging computes soff[j][w] = bias + 9-tap
// shift-add over S directly (each off channel consumed by exactly one
// block -> zero duplicated work). Core = r3 measured-best scalar gather.
// ---------------------------------------------------------------------------
__global__ __launch_bounds__(256) void sample_kernel(
    const float* __restrict__ x,
    const float* __restrict__ bs,
    float* __restrict__ out)
{
    __shared__ float soff[4][W_];   // j = kw*2+d for this kh

    const int b  = blockIdx.x;
    const int kh = b & 1;
    const int h  = (b >> 1) & (H_-1);
    const int n  = b >> 8;
    const int tid = threadIdx.x;

    // Fused shift-add staging: o = kh*4 + j
    const float* Sn = g_S + (size_t)n*NTP*HW;
    for (int i = tid; i < 4*W_; i += 256) {
        int j  = i >> 7;
        int ww = i & (W_-1);
        int o  = kh*4 + j;
        float s = __ldg(&bs[o]);
#pragma unroll
        for (int ky = 0; ky < 3; ky++) {
            const int hh = h + ky - 1;
            if ((unsigned)hh >= H_) continue;
#pragma unroll
            for (int kx = 0; kx < 3; kx++) {
                const int wx = ww + kx - 1;
                if ((unsigned)wx >= W_) continue;
                const int t = (ky*3 + kx)*8 + o;
                s += __ldg(&Sn[(size_t)t*HW + hh*W_ + wx]);
            }
        }
        soff[j][ww] = s;
    }
    __syncthreads();

    const int kw = tid & 1;
    const int w  = tid >> 1;

    float sy = (float)h + soff[kw*2    ][w];
    float sx = (float)w + soff[kw*2 + 1][w];
    float y0f = floorf(sy), x0f = floorf(sx);
    int   y0 = (int)y0f,   x0 = (int)x0f;
    float fy = sy - y0f,   fx = sx - x0f;

    float cw[4];
    cw[0] = (1.f - fy) * (1.f - fx);
    cw[1] = (1.f - fy) * fx;
    cw[2] = fy * (1.f - fx);
    cw[3] = fy * fx;
    int ci[4];
#pragma unroll
    for (int k = 0; k < 4; k++) {
        int yi = y0 + (k >> 1);
        int xi = x0 + (k & 1);
        bool valid = ((unsigned)yi < H_) && ((unsigned)xi < W_);
        int yc = min(max(yi, 0), H_-1);
        int xc = min(max(xi, 0), W_-1);
        ci[k] = yc*W_ + xc;
        if (!valid) cw[k] = 0.f;
    }

    const float* xp = x + (size_t)n*C_*HW;
    float* op = out + ((size_t)n*C_)*OH*OW + (size_t)(2*h + kh)*OW + (2*w + kw);

#pragma unroll 2
    for (int c = 0; c < C_; c++) {
        float v0 = __ldg(xp + ci[0]);
        float v1 = __ldg(xp + ci[1]);
        float v2 = __ldg(xp + ci[2]);
        float v3 = __ldg(xp + ci[3]);
        float r = v0*cw[0];
        r = fmaf(v1, cw[1], r);
        r = fmaf(v2, cw[2], r);
        r = fmaf(v3, cw[3], r);
        *op = r;
        xp += HW;
        op += OH*OW;
    }
}

// ---------------------------------------------------------------------------
extern "C" void kernel_launch(void* const* d_in, const int* in_sizes, int n_in,
                              void* d_out, int out_size)
{
    const float* x  = (const float*)d_in[0];
    const float* wt = (const float*)d_in[1];
    const float* bs = (const float*)d_in[2];
    float* out = (float*)d_out;

    cudaFuncSetAttribute(conv_gemm_kernel,
                         cudaFuncAttributeMaxDynamicSharedMemorySize, SM_TOT_B);

    conv_gemm_kernel<<<256, 256, SM_TOT_B>>>(x, wt);
    sample_kernel<<<N_*H_*2, 256>>>(x, bs, out);
}

// round 15
// speedup vs baseline: 2.3358x; 1.1424x over previous
#include <cuda_runtime.h>
#include <mma.h>
#include <cuda_fp16.h>
#include <cstdint>

using namespace nvcuda;

#define N_  4
#define C_  128
#define H_  128
#define W_  128
#define OC  8
#define OH  256
#define OW  256
#define HW  (H_*W_)
#define NT  72
#define NTP 80      // g_S t-stride
#define BLD 88      // smem B ldm (half; multiple of 8, bank-phase spread)

// S[n][t][hw], t = tap*8 + o  (t in [0,80), rows 72..79 pad)
__device__ float g_S[N_ * NTP * HW];

// ---------------------------------------------------------------------------
// Kernel 1: pointwise GEMM S[t,px] = sum_c W[t,c]*x[c,px], wmma fp16
// (m16n16k16, fp32 accum), 2x5 register blocking. Grid 256 = 4n x 64 tiles.
// fp16 mantissa == tf32 mantissa (10 bits) and operands are O(1)*O(0.01),
// so accuracy matches the tf32 version; mma + fragment-load count halves.
// ---------------------------------------------------------------------------
#define PXT  256
// halves: xt 64c x 256px, Wt 128c x BLD
#define SM_XT_H  0
#define SM_B_H   (64*PXT)
#define SM_TOT_B ((64*PXT + 128*BLD) * 2)

__global__ __launch_bounds__(256, 2) void conv_gemm_kernel(
    const float* __restrict__ x,
    const float* __restrict__ wt)    // [o][c][3][3]
{
    extern __shared__ __half smh[];
    __half* xt = smh + SM_XT_H;      // xt[c][px], c local in [0,64)
    __half* Wt = smh + SM_B_H;       // Wt[c][t],  c in [0,128), ldm=BLD

    const int tid = threadIdx.x;
    const int bid = blockIdx.x;
    const int n   = bid >> 6;
    const int px0 = (bid & 63) * PXT;
    const int wid = tid >> 5;

    // Stage B once: Wt[c][t] = wt[o][c][tap], t = tap*8+o (pad t>=72)
    for (int i = tid; i < 128*BLD; i += 256) {
        int c = i / BLD, t = i - c*BLD;
        float v = 0.f;
        if (t < NT) v = wt[(((size_t)(t & 7))*C_ + c)*9 + (t >> 3)];
        Wt[i] = __float2half(v);
    }

    wmma::fragment<wmma::accumulator, 16, 16, 16, float> acc[2][5];
#pragma unroll
    for (int i = 0; i < 2; i++)
#pragma unroll
        for (int tt = 0; tt < 5; tt++) wmma::fill_fragment(acc[i][tt], 0.f);

    const float* xn = x + (size_t)n*C_*HW + px0;

    for (int s = 0; s < 2; s++) {
        __syncthreads();
        // Stage 64 channels of x as half
        for (int i = tid; i < 64*(PXT/4); i += 256) {
            int c = i >> 6, p4 = (i & 63)*4;
            float4 v = *reinterpret_cast<const float4*>(xn + (size_t)(s*64 + c)*HW + p4);
            __half2* d = reinterpret_cast<__half2*>(xt + c*PXT + p4);
            d[0] = __floats2half2_rn(v.x, v.y);
            d[1] = __floats2half2_rn(v.z, v.w);
        }
        __syncthreads();

#pragma unroll
        for (int kl = 0; kl < 4; kl++) {    // 4 k-steps of 16
            wmma::fragment<wmma::matrix_a, 16, 16, 16, __half, wmma::col_major> a0, a1;
            wmma::load_matrix_sync(a0, xt + (kl*16)*PXT + 32*wid,      PXT);
            wmma::load_matrix_sync(a1, xt + (kl*16)*PXT + 32*wid + 16, PXT);
#pragma unroll
            for (int tt = 0; tt < 5; tt++) {
                wmma::fragment<wmma::matrix_b, 16, 16, 16, __half, wmma::row_major> b;
                wmma::load_matrix_sync(b, Wt + (s*64 + kl*16)*BLD + tt*16, BLD);
                wmma::mma_sync(acc[0][tt], a0, b, acc[0][tt]);
                wmma::mma_sync(acc[1][tt], a1, b, acc[1][tt]);
            }
        }
    }

    float* Sp = g_S + (size_t)n*NTP*HW + px0 + 32*wid;
#pragma unroll
    for (int i = 0; i < 2; i++)
#pragma unroll
        for (int tt = 0; tt < 5; tt++)
            wmma::store_matrix_sync(Sp + i*16 + (size_t)(tt*16)*HW, acc[i][tt],
                                    HW, wmma::mem_col_major);
}

// ---------------------------------------------------------------------------
// Kernel 2: fused shift-add + bilinear sampling + pixel shuffle.
// (r14 measured: 56.4 us) One block per (n, h, kh).
// ---------------------------------------------------------------------------
__global__ __launch_bounds__(256) void sample_kernel(
    const float* __restrict__ x,
    const float* __restrict__ bs,
    float* __restrict__ out)
{
    __shared__ float soff[4][W_];   // j = kw*2+d for this kh

    const int b  = blockIdx.x;
    const int kh = b & 1;
    const int h  = (b >> 1) & (H_-1);
    const int n  = b >> 8;
    const int tid = threadIdx.x;

    // Fused shift-add staging: o = kh*4 + j
    const float* Sn = g_S + (size_t)n*NTP*HW;
    for (int i = tid; i < 4*W_; i += 256) {
        int j  = i >> 7;
        int ww = i & (W_-1);
        int o  = kh*4 + j;
        float s = __ldg(&bs[o]);
#pragma unroll
        for (int ky = 0; ky < 3; ky++) {
            const int hh = h + ky - 1;
            if ((unsigned)hh >= H_) continue;
#pragma unroll
            for (int kx = 0; kx < 3; kx++) {
                const int wx = ww + kx - 1;
                if ((unsigned)wx >= W_) continue;
                const int t = (ky*3 + kx)*8 + o;
                s += __ldg(&Sn[(size_t)t*HW + hh*W_ + wx]);
            }
        }
        soff[j][ww] = s;
    }
    __syncthreads();

    const int kw = tid & 1;
    const int w  = tid >> 1;

    float sy = (float)h + soff[kw*2    ][w];
    float sx = (float)w + soff[kw*2 + 1][w];
    float y0f = floorf(sy), x0f = floorf(sx);
    int   y0 = (int)y0f,   x0 = (int)x0f;
    float fy = sy - y0f,   fx = sx - x0f;

    float cw[4];
    cw[0] = (1.f - fy) * (1.f - fx);
    cw[1] = (1.f - fy) * fx;
    cw[2] = fy * (1.f - fx);
    cw[3] = fy * fx;
    int ci[4];
#pragma unroll
    for (int k = 0; k < 4; k++) {
        int yi = y0 + (k >> 1);
        int xi = x0 + (k & 1);
        bool valid = ((unsigned)yi < H_) && ((unsigned)xi < W_);
        int yc = min(max(yi, 0), H_-1);
        int xc = min(max(xi, 0), W_-1);
        ci[k] = yc*W_ + xc;
        if (!valid) cw[k] = 0.f;
    }

    const float* xp = x + (size_t)n*C_*HW;
    float* op = out + ((size_t)n*C_)*OH*OW + (size_t)(2*h + kh)*OW + (2*w + kw);

#pragma unroll 2
    for (int c = 0; c < C_; c++) {
        float v0 = __ldg(xp + ci[0]);
        float v1 = __ldg(xp + ci[1]);
        float v2 = __ldg(xp + ci[2]);
        float v3 = __ldg(xp + ci[3]);
        float r = v0*cw[0];
        r = fmaf(v1, cw[1], r);
        r = fmaf(v2, cw[2], r);
        r = fmaf(v3, cw[3], r);
        *op = r;
        xp += HW;
        op += OH*OW;
    }
}

// ---------------------------------------------------------------------------
extern "C" void kernel_launch(void* const* d_in, const int* in_sizes, int n_in,
                              void* d_out, int out_size)
{
    const float* x  = (const float*)d_in[0];
    const float* wt = (const float*)d_in[1];
    const float* bs = (const float*)d_in[2];
    float* out = (float*)d_out;

    cudaFuncSetAttribute(conv_gemm_kernel,
                         cudaFuncAttributeMaxDynamicSharedMemorySize, SM_TOT_B);

    conv_gemm_kernel<<<256, 256, SM_TOT_B>>>(x, wt);
    sample_kernel<<<N_*H_*2, 256>>>(x, bs, out);
}

// round 16
// speedup vs baseline: 2.6743x; 1.1449x over previous
#include <cuda_runtime.h>
#include <mma.h>
#include <cuda_fp16.h>
#include <cstdint>

using namespace nvcuda;

#define N_  4
#define C_  128
#define H_  128
#define W_  128
#define OC  8
#define OH  256
#define OW  256
#define HW  (H_*W_)
#define NT  72
#define NTP 80      // g_S t-stride
#define BLD 88      // smem B ldm (half; multiple of 8)

// S[n][t][hw], t = tap*8 + o  (t in [0,80), rows 72..79 pad)
__device__ float g_S[N_ * NTP * HW];
// packed x: [n][c2][hw] with half2 = (x[2*c2], x[2*c2+1])
__device__ __half2 g_xh[N_ * (C_/2) * HW];

// ---------------------------------------------------------------------------
// Kernel 1: pointwise GEMM S[t,px] = sum_c W[t,c]*x[c,px], wmma fp16
// (m16n16k16, fp32 accum), 2x5 register blocking. Grid 256 = 4n x 64 tiles.
// Side effect: writes the channel-pair-packed half2 copy of x (g_xh) that
// the sample kernel gathers from (each x element staged exactly once).
// ---------------------------------------------------------------------------
#define PXT  256
#define SM_XT_H  0
#define SM_B_H   (64*PXT)
#define SM_TOT_B ((64*PXT + 128*BLD) * 2)

__global__ __launch_bounds__(256, 2) void conv_gemm_kernel(
    const float* __restrict__ x,
    const float* __restrict__ wt)    // [o][c][3][3]
{
    extern __shared__ __half smh[];
    __half* xt = smh + SM_XT_H;      // xt[c][px], c local in [0,64)
    __half* Wt = smh + SM_B_H;       // Wt[c][t],  c in [0,128), ldm=BLD

    const int tid = threadIdx.x;
    const int bid = blockIdx.x;
    const int n   = bid >> 6;
    const int px0 = (bid & 63) * PXT;
    const int wid = tid >> 5;

    // Stage B once: Wt[c][t] = wt[o][c][tap], t = tap*8+o (pad t>=72)
    for (int i = tid; i < 128*BLD; i += 256) {
        int c = i / BLD, t = i - c*BLD;
        float v = 0.f;
        if (t < NT) v = wt[(((size_t)(t & 7))*C_ + c)*9 + (t >> 3)];
        Wt[i] = __float2half(v);
    }

    wmma::fragment<wmma::accumulator, 16, 16, 16, float> acc[2][5];
#pragma unroll
    for (int i = 0; i < 2; i++)
#pragma unroll
        for (int tt = 0; tt < 5; tt++) wmma::fill_fragment(acc[i][tt], 0.f);

    const float* xn = x + (size_t)n*C_*HW + px0;
    __half2* xhn = g_xh + (size_t)n*(C_/2)*HW + px0;

    for (int s = 0; s < 2; s++) {
        __syncthreads();
        // Stage 64 channels as half into smem AND write packed half2 copy.
        // i: c2 = pair 0..31 (global channels s*64+2c2, +1), p4 = px quad.
        for (int i = tid; i < 32*64; i += 256) {
            int c2 = i >> 6, p4 = (i & 63)*4;
            float4 a = *reinterpret_cast<const float4*>(xn + (size_t)(s*64 + 2*c2    )*HW + p4);
            float4 b = *reinterpret_cast<const float4*>(xn + (size_t)(s*64 + 2*c2 + 1)*HW + p4);
            __half2* d0 = reinterpret_cast<__half2*>(xt + (2*c2    )*PXT + p4);
            __half2* d1 = reinterpret_cast<__half2*>(xt + (2*c2 + 1)*PXT + p4);
            d0[0] = __floats2half2_rn(a.x, a.y);
            d0[1] = __floats2half2_rn(a.z, a.w);
            d1[0] = __floats2half2_rn(b.x, b.y);
            d1[1] = __floats2half2_rn(b.z, b.w);
            __half2* xo = xhn + (size_t)(s*32 + c2)*HW + p4;
            xo[0] = __floats2half2_rn(a.x, b.x);
            xo[1] = __floats2half2_rn(a.y, b.y);
            xo[2] = __floats2half2_rn(a.z, b.z);
            xo[3] = __floats2half2_rn(a.w, b.w);
        }
        __syncthreads();

#pragma unroll
        for (int kl = 0; kl < 4; kl++) {    // 4 k-steps of 16
            wmma::fragment<wmma::matrix_a, 16, 16, 16, __half, wmma::col_major> a0, a1;
            wmma::load_matrix_sync(a0, xt + (kl*16)*PXT + 32*wid,      PXT);
            wmma::load_matrix_sync(a1, xt + (kl*16)*PXT + 32*wid + 16, PXT);
#pragma unroll
            for (int tt = 0; tt < 5; tt++) {
                wmma::fragment<wmma::matrix_b, 16, 16, 16, __half, wmma::row_major> b;
                wmma::load_matrix_sync(b, Wt + (s*64 + kl*16)*BLD + tt*16, BLD);
                wmma::mma_sync(acc[0][tt], a0, b, acc[0][tt]);
                wmma::mma_sync(acc[1][tt], a1, b, acc[1][tt]);
            }
        }
    }

    float* Sp = g_S + (size_t)n*NTP*HW + px0 + 32*wid;
#pragma unroll
    for (int i = 0; i < 2; i++)
#pragma unroll
        for (int tt = 0; tt < 5; tt++)
            wmma::store_matrix_sync(Sp + i*16 + (size_t)(tt*16)*HW, acc[i][tt],
                                    HW, wmma::mem_col_major);
}

// ---------------------------------------------------------------------------
// Kernel 2: fused shift-add + bilinear sampling + pixel shuffle, gathering
// from the half2 channel-pair-packed x: one 4B gather serves 2 channels ->
// 64-iteration channel loop, gather wavefronts halved.
// One block per (n, h, kh): 256 threads, tid = w*2 + kw.
// ---------------------------------------------------------------------------
__global__ __launch_bounds__(256) void sample_kernel(
    const float* __restrict__ bs,
    float* __restrict__ out)
{
    __shared__ float soff[4][W_];   // j = kw*2+d for this kh

    const int b  = blockIdx.x;
    const int kh = b & 1;
    const int h  = (b >> 1) & (H_-1);
    const int n  = b >> 8;
    const int tid = threadIdx.x;

    // Fused shift-add staging: o = kh*4 + j
    const float* Sn = g_S + (size_t)n*NTP*HW;
    for (int i = tid; i < 4*W_; i += 256) {
        int j  = i >> 7;
        int ww = i & (W_-1);
        int o  = kh*4 + j;
        float s = __ldg(&bs[o]);
#pragma unroll
        for (int ky = 0; ky < 3; ky++) {
            const int hh = h + ky - 1;
            if ((unsigned)hh >= H_) continue;
#pragma unroll
            for (int kx = 0; kx < 3; kx++) {
                const int wx = ww + kx - 1;
                if ((unsigned)wx >= W_) continue;
                const int t = (ky*3 + kx)*8 + o;
                s += __ldg(&Sn[(size_t)t*HW + hh*W_ + wx]);
            }
        }
        soff[j][ww] = s;
    }
    __syncthreads();

    const int kw = tid & 1;
    const int w  = tid >> 1;

    float sy = (float)h + soff[kw*2    ][w];
    float sx = (float)w + soff[kw*2 + 1][w];
    float y0f = floorf(sy), x0f = floorf(sx);
    int   y0 = (int)y0f,   x0 = (int)x0f;
    float fy = sy - y0f,   fx = sx - x0f;

    float cw[4];
    cw[0] = (1.f - fy) * (1.f - fx);
    cw[1] = (1.f - fy) * fx;
    cw[2] = fy * (1.f - fx);
    cw[3] = fy * fx;
    int ci[4];
#pragma unroll
    for (int k = 0; k < 4; k++) {
        int yi = y0 + (k >> 1);
        int xi = x0 + (k & 1);
        bool valid = ((unsigned)yi < H_) && ((unsigned)xi < W_);
        int yc = min(max(yi, 0), H_-1);
        int xc = min(max(xi, 0), W_-1);
        ci[k] = yc*W_ + xc;
        if (!valid) cw[k] = 0.f;
    }

    const __half2* xp = g_xh + (size_t)n*(C_/2)*HW;
    float* op = out + ((size_t)n*C_)*OH*OW + (size_t)(2*h + kh)*OW + (2*w + kw);

#pragma unroll 2
    for (int c2 = 0; c2 < C_/2; c2++) {
        __half2 u0 = __ldg(xp + ci[0]);
        __half2 u1 = __ldg(xp + ci[1]);
        __half2 u2 = __ldg(xp + ci[2]);
        __half2 u3 = __ldg(xp + ci[3]);
        float2 f0 = __half22float2(u0);
        float2 f1 = __half22float2(u1);
        float2 f2 = __half22float2(u2);
        float2 f3 = __half22float2(u3);

        float rl = f0.x*cw[0];
        rl = fmaf(f1.x, cw[1], rl);
        rl = fmaf(f2.x, cw[2], rl);
        rl = fmaf(f3.x, cw[3], rl);
        float rh = f0.y*cw[0];
        rh = fmaf(f1.y, cw[1], rh);
        rh = fmaf(f2.y, cw[2], rh);
        rh = fmaf(f3.y, cw[3], rh);

        op[0]                 = rl;
        op[(size_t)OH*OW]     = rh;
        xp += HW;
        op += (size_t)2*OH*OW;
    }
}

// ---------------------------------------------------------------------------
extern "C" void kernel_launch(void* const* d_in, const int* in_sizes, int n_in,
                              void* d_out, int out_size)
{
    const float* x  = (const float*)d_in[0];
    const float* wt = (const float*)d_in[1];
    const float* bs = (const float*)d_in[2];
    float* out = (float*)d_out;

    cudaFuncSetAttribute(conv_gemm_kernel,
                         cudaFuncAttributeMaxDynamicSharedMemorySize, SM_TOT_B);

    conv_gemm_kernel<<<256, 256, SM_TOT_B>>>(x, wt);
    sample_kernel<<<N_*H_*2, 256>>>(bs, out);
}

// round 17
// speedup vs baseline: 3.0768x; 1.1505x over previous
#include <cuda_runtime.h>
#include <mma.h>
#include <cuda_fp16.h>
#include <cstdint>

using namespace nvcuda;

#define N_  4
#define C_  128
#define H_  128
#define W_  128
#define OC  8
#define OH  256
#define OW  256
#define HW  (H_*W_)
#define NT  72
#define NTP 80      // g_S t-stride
#define BLD 88      // smem B ldm (half; multiple of 8)

// S[n][t][hw], t = tap*8 + o  (t in [0,80), rows 72..79 pad)
__device__ float g_S[N_ * NTP * HW];
// packed x: [n][c4][hw], uint2 = 4 halves = channels (4c4, 4c4+1, 4c4+2, 4c4+3)
__device__ uint2 g_xh4[N_ * (C_/4) * HW];

// ---------------------------------------------------------------------------
// Kernel 1: pointwise GEMM S[t,px] = sum_c W[t,c]*x[c,px], wmma fp16
// (m16n16k16, fp32 accum), 2x5 register blocking, single-stage K (all 128
// channels resident; one barrier, 32-deep staging MLP). Side effect: writes
// the 4-channel-packed half copy of x (g_xh4). Grid 256 = 4n x 64 tiles.
// ---------------------------------------------------------------------------
#define PXT  256
#define SM_XT_H  0                   // 128c x 256px halves
#define SM_B_H   (128*PXT)           // 128c x BLD halves
#define SM_TOT_B ((128*PXT + 128*BLD) * 2)

__global__ __launch_bounds__(256, 2) void conv_gemm_kernel(
    const float* __restrict__ x,
    const float* __restrict__ wt)    // [o][c][3][3]
{
    extern __shared__ __half smh[];
    __half* xt = smh + SM_XT_H;      // xt[c][px]
    __half* Wt = smh + SM_B_H;       // Wt[c][t], ldm=BLD

    const int tid = threadIdx.x;
    const int bid = blockIdx.x;
    const int n   = bid >> 6;
    const int px0 = (bid & 63) * PXT;
    const int wid = tid >> 5;

    // Stage B: Wt[c][t] = wt[o][c][tap], t = tap*8+o (pad t>=72)
    for (int i = tid; i < 128*BLD; i += 256) {
        int c = i / BLD, t = i - c*BLD;
        float v = 0.f;
        if (t < NT) v = wt[(((size_t)(t & 7))*C_ + c)*9 + (t >> 3)];
        Wt[i] = __float2half(v);
    }

    // Stage x (all 128 channels) + write 4-channel-packed copy
    const float* xn = x + (size_t)n*C_*HW + px0;
    uint2* xpk = g_xh4 + (size_t)n*(C_/4)*HW + px0;
    for (int i = tid; i < 32*64; i += 256) {
        int c4 = i >> 6, p4 = (i & 63)*4;
        float4 v0 = *reinterpret_cast<const float4*>(xn + (size_t)(4*c4    )*HW + p4);
        float4 v1 = *reinterpret_cast<const float4*>(xn + (size_t)(4*c4 + 1)*HW + p4);
        float4 v2 = *reinterpret_cast<const float4*>(xn + (size_t)(4*c4 + 2)*HW + p4);
        float4 v3 = *reinterpret_cast<const float4*>(xn + (size_t)(4*c4 + 3)*HW + p4);

        __half2* d0 = reinterpret_cast<__half2*>(xt + (4*c4    )*PXT + p4);
        __half2* d1 = reinterpret_cast<__half2*>(xt + (4*c4 + 1)*PXT + p4);
        __half2* d2 = reinterpret_cast<__half2*>(xt + (4*c4 + 2)*PXT + p4);
        __half2* d3 = reinterpret_cast<__half2*>(xt + (4*c4 + 3)*PXT + p4);
        d0[0] = __floats2half2_rn(v0.x, v0.y); d0[1] = __floats2half2_rn(v0.z, v0.w);
        d1[0] = __floats2half2_rn(v1.x, v1.y); d1[1] = __floats2half2_rn(v1.z, v1.w);
        d2[0] = __floats2half2_rn(v2.x, v2.y); d2[1] = __floats2half2_rn(v2.z, v2.w);
        d3[0] = __floats2half2_rn(v3.x, v3.y); d3[1] = __floats2half2_rn(v3.z, v3.w);

        uint2* xo = xpk + (size_t)c4*HW + p4;
        {
            __half2 lo, hi; uint2 u;
            lo = __floats2half2_rn(v0.x, v1.x); hi = __floats2half2_rn(v2.x, v3.x);
            u.x = *reinterpret_cast<uint32_t*>(&lo); u.y = *reinterpret_cast<uint32_t*>(&hi); xo[0] = u;
            lo = __floats2half2_rn(v0.y, v1.y); hi = __floats2half2_rn(v2.y, v3.y);
            u.x = *reinterpret_cast<uint32_t*>(&lo); u.y = *reinterpret_cast<uint32_t*>(&hi); xo[1] = u;
            lo = __floats2half2_rn(v0.z, v1.z); hi = __floats2half2_rn(v2.z, v3.z);
            u.x = *reinterpret_cast<uint32_t*>(&lo); u.y = *reinterpret_cast<uint32_t*>(&hi); xo[2] = u;
            lo = __floats2half2_rn(v0.w, v1.w); hi = __floats2half2_rn(v2.w, v3.w);
            u.x = *reinterpret_cast<uint32_t*>(&lo); u.y = *reinterpret_cast<uint32_t*>(&hi); xo[3] = u;
        }
    }
    __syncthreads();

    wmma::fragment<wmma::accumulator, 16, 16, 16, float> acc[2][5];
#pragma unroll
    for (int i = 0; i < 2; i++)
#pragma unroll
        for (int tt = 0; tt < 5; tt++) wmma::fill_fragment(acc[i][tt], 0.f);

#pragma unroll
    for (int kl = 0; kl < 8; kl++) {    // 8 k-steps of 16
        wmma::fragment<wmma::matrix_a, 16, 16, 16, __half, wmma::col_major> a0, a1;
        wmma::load_matrix_sync(a0, xt + (kl*16)*PXT + 32*wid,      PXT);
        wmma::load_matrix_sync(a1, xt + (kl*16)*PXT + 32*wid + 16, PXT);
#pragma unroll
        for (int tt = 0; tt < 5; tt++) {
            wmma::fragment<wmma::matrix_b, 16, 16, 16, __half, wmma::row_major> b;
            wmma::load_matrix_sync(b, Wt + (kl*16)*BLD + tt*16, BLD);
            wmma::mma_sync(acc[0][tt], a0, b, acc[0][tt]);
            wmma::mma_sync(acc[1][tt], a1, b, acc[1][tt]);
        }
    }

    float* Sp = g_S + (size_t)n*NTP*HW + px0 + 32*wid;
#pragma unroll
    for (int i = 0; i < 2; i++)
#pragma unroll
        for (int tt = 0; tt < 5; tt++)
            wmma::store_matrix_sync(Sp + i*16 + (size_t)(tt*16)*HW, acc[i][tt],
                                    HW, wmma::mem_col_major);
}

// ---------------------------------------------------------------------------
// Kernel 2: fused shift-add + bilinear sampling + pixel shuffle, gathering
// from 4-channel-packed x: one 8B gather serves 4 channels -> 32-iteration
// channel loop. One block per (n, h, kh): 256 threads, tid = w*2 + kw.
// ---------------------------------------------------------------------------
__global__ __launch_bounds__(256) void sample_kernel(
    const float* __restrict__ bs,
    float* __restrict__ out)
{
    __shared__ float soff[4][W_];   // j = kw*2+d for this kh

    const int b  = blockIdx.x;
    const int kh = b & 1;
    const int h  = (b >> 1) & (H_-1);
    const int n  = b >> 8;
    const int tid = threadIdx.x;

    // Fused shift-add staging: o = kh*4 + j
    const float* Sn = g_S + (size_t)n*NTP*HW;
    for (int i = tid; i < 4*W_; i += 256) {
        int j  = i >> 7;
        int ww = i & (W_-1);
        int o  = kh*4 + j;
        float s = __ldg(&bs[o]);
#pragma unroll
        for (int ky = 0; ky < 3; ky++) {
            const int hh = h + ky - 1;
            if ((unsigned)hh >= H_) continue;
#pragma unroll
            for (int kx = 0; kx < 3; kx++) {
                const int wx = ww + kx - 1;
                if ((unsigned)wx >= W_) continue;
                const int t = (ky*3 + kx)*8 + o;
                s += __ldg(&Sn[(size_t)t*HW + hh*W_ + wx]);
            }
        }
        soff[j][ww] = s;
    }
    __syncthreads();

    const int kw = tid & 1;
    const int w  = tid >> 1;

    float sy = (float)h + soff[kw*2    ][w];
    float sx = (float)w + soff[kw*2 + 1][w];
    float y0f = floorf(sy), x0f = floorf(sx);
    int   y0 = (int)y0f,   x0 = (int)x0f;
    float fy = sy - y0f,   fx = sx - x0f;

    float cw[4];
    cw[0] = (1.f - fy) * (1.f - fx);
    cw[1] = (1.f - fy) * fx;
    cw[2] = fy * (1.f - fx);
    cw[3] = fy * fx;
    int ci[4];
#pragma unroll
    for (int k = 0; k < 4; k++) {
        int yi = y0 + (k >> 1);
        int xi = x0 + (k & 1);
        bool valid = ((unsigned)yi < H_) && ((unsigned)xi < W_);
        int yc = min(max(yi, 0), H_-1);
        int xc = min(max(xi, 0), W_-1);
        ci[k] = yc*W_ + xc;
        if (!valid) cw[k] = 0.f;
    }

    const uint2* xp = g_xh4 + (size_t)n*(C_/4)*HW;
    float* op = out + ((size_t)n*C_)*OH*OW + (size_t)(2*h + kh)*OW + (2*w + kw);

#pragma unroll 2
    for (int c4 = 0; c4 < C_/4; c4++) {
        uint2 u0 = __ldg(xp + ci[0]);
        uint2 u1 = __ldg(xp + ci[1]);
        uint2 u2 = __ldg(xp + ci[2]);
        uint2 u3 = __ldg(xp + ci[3]);

        float2 a0 = __half22float2(*reinterpret_cast<__half2*>(&u0.x));
        float2 b0 = __half22float2(*reinterpret_cast<__half2*>(&u0.y));
        float2 a1 = __half22float2(*reinterpret_cast<__half2*>(&u1.x));
        float2 b1 = __half22float2(*reinterpret_cast<__half2*>(&u1.y));
        float2 a2 = __half22float2(*reinterpret_cast<__half2*>(&u2.x));
        float2 b2 = __half22float2(*reinterpret_cast<__half2*>(&u2.y));
        float2 a3 = __half22float2(*reinterpret_cast<__half2*>(&u3.x));
        float2 b3 = __half22float2(*reinterpret_cast<__half2*>(&u3.y));

        float r0 = a0.x*cw[0];
        r0 = fmaf(a1.x, cw[1], r0); r0 = fmaf(a2.x, cw[2], r0); r0 = fmaf(a3.x, cw[3], r0);
        float r1 = a0.y*cw[0];
        r1 = fmaf(a1.y, cw[1], r1); r1 = fmaf(a2.y, cw[2], r1); r1 = fmaf(a3.y, cw[3], r1);
        float r2 = b0.x*cw[0];
        r2 = fmaf(b1.x, cw[1], r2); r2 = fmaf(b2.x, cw[2], r2); r2 = fmaf(b3.x, cw[3], r2);
        float r3 = b0.y*cw[0];
        r3 = fmaf(b1.y, cw[1], r3); r3 = fmaf(b2.y, cw[2], r3); r3 = fmaf(b3.y, cw[3], r3);

        op[0]                   = r0;
        op[(size_t)OH*OW]       = r1;
        op[(size_t)2*OH*OW]     = r2;
        op[(size_t)3*OH*OW]     = r3;
        xp += HW;
        op += (size_t)4*OH*OW;
    }
}

// ---------------------------------------------------------------------------
extern "C" void kernel_launch(void* const* d_in, const int* in_sizes, int n_in,
                              void* d_out, int out_size)
{
    const float* x  = (const float*)d_in[0];
    const float* wt = (const float*)d_in[1];
    const float* bs = (const float*)d_in[2];
    float* out = (float*)d_out;

    cudaFuncSetAttribute(conv_gemm_kernel,
                         cudaFuncAttributeMaxDynamicSharedMemorySize, SM_TOT_B);

    conv_gemm_kernel<<<256, 256, SM_TOT_B>>>(x, wt);
    sample_kernel<<<N_*H_*2, 256>>>(bs, out);
}